// round 15
// baseline (speedup 1.0000x reference)
#include <cuda_runtime.h>
#include <cuda_bf16.h>

// LinearSpline activation, division-free, channel-folded:
//   t  = x * (s[c]*6.25f)                 (6.25f == float(1/0.16), exact)
//   tc = clamp(t, -25.0f, 24.0f)          (== reference clip-then-divide)
//   ip = (int)floor(tc);  fr = t - ip     (fr from unclamped t, per reference)
//   out = fma(fr, C1-C0, C0)   where (C0,C1) = (c[z+ip]/s, c[z+ip+1]/s)
//
// R15 = R14 (best: __ldlu loads + __stcs stores, 2 CTAs x 768, 13KB table,
// in-place chain) + DRAM-locality pairing: the ILP2 pair is block-contiguous
// (thread t handles base+t and base+t+768) so each CTA trip covers one
// contiguous 96KB chunk instead of two regions 3.6MB apart. Halves the
// number of simultaneously-active DRAM regions -> better row-buffer hits.

#define NUM_ACT 64
#define SIZE    51
#define TABLE   (NUM_ACT * SIZE)   // 3264

__global__ __launch_bounds__(768, 2)
void linear_spline_kernel(const float4* __restrict__ x,
                          const float*  __restrict__ coef,
                          const float*  __restrict__ scale,
                          float4*       __restrict__ out,
                          int n4)
{
    __shared__ float sc[TABLE + 1];     // c[i]/s[c], 13.3 KB (+1 pad for v4 fill)
    __shared__ float s625[NUM_ACT];     // s[c] * 6.25f
    __shared__ float srs[NUM_ACT];      // 1/s[c]

    if (threadIdx.x < NUM_ACT) {
        float s = scale[threadIdx.x];
        srs[threadIdx.x]  = 1.0f / s;        // exact for s==1
        s625[threadIdx.x] = s * 6.25f;       // exact for s==1
    }
    __syncthreads();

    // Vectorized table load: 816 float4 = 3264 floats; 1 division per channel.
    {
        const float4* c4 = (const float4*)coef;
        for (int q = threadIdx.x; q < TABLE / 4; q += 768) {
            float4 v = c4[q];
            int i0 = q * 4;
            sc[i0]     = v.x * srs[(i0)     / SIZE];
            sc[i0 + 1] = v.y * srs[(i0 + 1) / SIZE];
            sc[i0 + 2] = v.z * srs[(i0 + 2) / SIZE];
            sc[i0 + 3] = v.w * srs[(i0 + 3) / SIZE];
        }
    }
    __syncthreads();

    // Block-contiguous pairing: each CTA trip covers a contiguous 1536-float4
    // chunk; thread t handles chunk+t and chunk+t+768 (12KB apart in-warp).
    const int chunk  = 2 * 768;                    // float4 per CTA trip
    const int cstep  = gridDim.x * chunk;          // grid advance per trip

    // ~10 warp-ops + 2 LDS.32 per element; in-place result. Max idx = 3263.
    #define ELEM(v, zk_, sg_) {                          \
        float t  = (v) * (sg_);                          \
        float tc = fminf(fmaxf(t, -25.0f), 24.0f);       \
        int   ip = __float2int_rd(tc);                   \
        float fr = t - (float)ip;                        \
        int p = (zk_) + ip;                              \
        float c0 = sc[p];                                \
        float c1 = sc[p + 1];                            \
        (v) = fmaf(fr, c1 - c0, c0); }

    for (int base = blockIdx.x * chunk; base < n4; base += cstep) {
        const int i = base + threadIdx.x;
        const int j = i + 768;
        // n4 = 8,388,608 is divisible by 1536? 8388608/1536 = 5461.33 — not
        // exact, so guard both lanes.
        float4 xa, xb;
        const bool va = (i < n4);
        const bool vb = (j < n4);
        if (va) xa = __ldlu(&x[i]);
        if (vb) xb = __ldlu(&x[j]);

        if (va) {
            const int ca = (i >> 12) & (NUM_ACT - 1);   // 4096 float4 per channel
            const float sga = s625[ca];
            const int zka = ca * SIZE + SIZE / 2;
            ELEM(xa.x, zka, sga)
            ELEM(xa.y, zka, sga)
            ELEM(xa.z, zka, sga)
            ELEM(xa.w, zka, sga)
            __stcs(&out[i], xa);
        }
        if (vb) {
            const int cb = (j >> 12) & (NUM_ACT - 1);
            const float sgb = s625[cb];
            const int zkb = cb * SIZE + SIZE / 2;
            ELEM(xb.x, zkb, sgb)
            ELEM(xb.y, zkb, sgb)
            ELEM(xb.z, zkb, sgb)
            ELEM(xb.w, zkb, sgb)
            __stcs(&out[j], xb);
        }
    }
    #undef ELEM
}

extern "C" void kernel_launch(void* const* d_in, const int* in_sizes, int n_in,
                              void* d_out, int out_size)
{
    const float* x     = (const float*)d_in[0];
    const float* coef  = (const float*)d_in[1];
    const float* scale = (const float*)d_in[2];
    float* out         = (float*)d_out;

    const int n  = in_sizes[0];   // 33,554,432
    const int n4 = n / 4;         // 8,388,608

    const int threads = 768;
    const int blocks  = 148 * 2;  // 2 CTAs/SM = 48 warps, 13KB smem, L1 ~200KB

    linear_spline_kernel<<<blocks, threads>>>(
        (const float4*)x, coef, scale, (float4*)out, n4);
}